// round 10
// baseline (speedup 1.0000x reference)
#include <cuda_runtime.h>
#include <cstdint>

// Bayer mosaic channel select:
//   out[b,i,j] = img[b, c, i, j]
//   c = 1 if (i+j) even; else 2 if i even; else 0
// Row-parity view:
//   i even: j even -> ch1, j odd -> ch2
//   i odd : j even -> ch0, j odd -> ch1
//
// R10: Blackwell 256-bit global accesses (ld/st.global.v8.f32, sm_100+).
// One CTA per image row, 256 threads, each thread one 32B sector (8 floats):
//   2x LDG.256 (one per relevant channel plane) + 1x STG.256.
// Same contiguous per-CTA extents as the converged R6/R8 kernel; half the
// memory instructions and L1tex wavefront-queue entries per byte.

static constexpr unsigned H = 2048;
static constexpr unsigned W = 2048;
static constexpr unsigned PLANE = H * W;         // 4,194,304 elements

struct __align__(32) f8 { float v[8]; };

__device__ __forceinline__ f8 ldg256(const float* p) {
    f8 r;
    asm volatile("ld.global.v8.f32 {%0,%1,%2,%3,%4,%5,%6,%7}, [%8];"
                 : "=f"(r.v[0]), "=f"(r.v[1]), "=f"(r.v[2]), "=f"(r.v[3]),
                   "=f"(r.v[4]), "=f"(r.v[5]), "=f"(r.v[6]), "=f"(r.v[7])
                 : "l"(p));
    return r;
}

__device__ __forceinline__ void stg256(float* p, const f8& r) {
    asm volatile("st.global.v8.f32 [%0], {%1,%2,%3,%4,%5,%6,%7,%8};"
                 :: "l"(p),
                    "f"(r.v[0]), "f"(r.v[1]), "f"(r.v[2]), "f"(r.v[3]),
                    "f"(r.v[4]), "f"(r.v[5]), "f"(r.v[6]), "f"(r.v[7])
                 : "memory");
}

__global__ __launch_bounds__(256)
void bayer_kernel(const float* __restrict__ img, float* __restrict__ out) {
    const unsigned j  = threadIdx.x << 3;        // element index within row (8/thread)
    const unsigned i  = blockIdx.x;              // row
    const unsigned b  = blockIdx.y;              // batch
    const unsigned sub = i & 1u;                 // 0: even row, 1: odd row

    // cA serves even j (even row -> ch1, odd row -> ch0); cB = cA + 1 always.
    const unsigned cA = 1u - sub;
    const unsigned row_base = (b * 3u + cA) * PLANE + i * W + j;

    const f8 a  = ldg256(img + row_base);            // cA plane
    const f8 bv = ldg256(img + row_base + PLANE);    // cB plane

    f8 o;
    #pragma unroll
    for (int k = 0; k < 8; k += 2) {
        o.v[k]     = a.v[k];       // even j
        o.v[k + 1] = bv.v[k + 1];  // odd j
    }

    stg256(out + (b * H + i) * W + j, o);
}

extern "C" void kernel_launch(void* const* d_in, const int* in_sizes, int n_in,
                              void* d_out, int out_size) {
    const float* img = (const float*)d_in[0];
    float* out = (float*)d_out;

    dim3 grid(H, 8);     // (2048 rows, 8 batches) = 16384 CTAs of 256 threads
    bayer_kernel<<<grid, 256>>>(img, out);
}

// round 11
// speedup vs baseline: 1.0041x; 1.0041x over previous
#include <cuda_runtime.h>
#include <cstdint>

// Bayer mosaic channel select:
//   out[b,i,j] = img[b, c, i, j]
//   c = 1 if (i+j) even; else 2 if i even; else 0
// Row-parity view:
//   i even: j even -> ch1, j odd -> ch2
//   i odd : j even -> ch0, j odd -> ch1
//
// R11: Blackwell 256-bit accesses (best ncu: 54.1us) + row-pair CTA at the
// proven 512-thread block size. Each thread: one 32B sector (8 floats),
// 2x LDG.256 + 1x STG.256. Per-CTA extents:
//   read  ch1 rows [i,i+1] -> 16 KB contiguous (both parities use ch1)
//   read  ch2 row i        ->  8 KB contiguous
//   read  ch0 row i+1      ->  8 KB contiguous
//   write out rows [i,i+1] -> 16 KB contiguous

static constexpr unsigned H = 2048;
static constexpr unsigned W = 2048;
static constexpr unsigned PLANE = H * W;         // 4,194,304 elements
static constexpr unsigned W8 = W / 8;            // 256 sectors per row

struct __align__(32) f8 { float v[8]; };

__device__ __forceinline__ f8 ldg256(const float* p) {
    f8 r;
    asm volatile("ld.global.v8.f32 {%0,%1,%2,%3,%4,%5,%6,%7}, [%8];"
                 : "=f"(r.v[0]), "=f"(r.v[1]), "=f"(r.v[2]), "=f"(r.v[3]),
                   "=f"(r.v[4]), "=f"(r.v[5]), "=f"(r.v[6]), "=f"(r.v[7])
                 : "l"(p));
    return r;
}

__device__ __forceinline__ void stg256(float* p, const f8& r) {
    asm volatile("st.global.v8.f32 [%0], {%1,%2,%3,%4,%5,%6,%7,%8};"
                 :: "l"(p),
                    "f"(r.v[0]), "f"(r.v[1]), "f"(r.v[2]), "f"(r.v[3]),
                    "f"(r.v[4]), "f"(r.v[5]), "f"(r.v[6]), "f"(r.v[7])
                 : "memory");
}

__global__ __launch_bounds__(512)
void bayer_kernel(const float* __restrict__ img, float* __restrict__ out) {
    const unsigned t   = threadIdx.x;            // [0,512)
    const unsigned sub = t >> 8;                 // 0: even row of pair, 1: odd
    const unsigned j   = (t & (W8 - 1u)) << 3;   // element index within row
    const unsigned i   = (blockIdx.x << 1) | sub;  // actual row
    const unsigned b   = blockIdx.y;             // batch

    // cA serves even j (even row -> ch1, odd row -> ch0); cB = cA + 1 always.
    const unsigned cA = 1u - sub;
    const unsigned row_base = (b * 3u + cA) * PLANE + i * W + j;

    const f8 a  = ldg256(img + row_base);            // cA plane
    const f8 bv = ldg256(img + row_base + PLANE);    // cB plane

    f8 o;
    #pragma unroll
    for (int k = 0; k < 8; k += 2) {
        o.v[k]     = a.v[k];       // even j
        o.v[k + 1] = bv.v[k + 1];  // odd j
    }

    stg256(out + (b * H + i) * W + j, o);
}

extern "C" void kernel_launch(void* const* d_in, const int* in_sizes, int n_in,
                              void* d_out, int out_size) {
    const float* img = (const float*)d_in[0];
    float* out = (float*)d_out;

    dim3 grid(H / 2, 8);    // (1024 row-pairs, 8 batches) = 8192 CTAs of 512
    bayer_kernel<<<grid, 512>>>(img, out);
}